// round 3
// baseline (speedup 1.0000x reference)
#include <cuda_runtime.h>
#include <cstddef>

#define BSZ   256
#define NN    2048
#define KK    64
#define KP1   65
#define NT    256
#define RPT   8          // rows per thread = NN/NT
#define NWARP (NT/32)    // 8
#define RSTR  65         // padded stride for reduction rows (odd -> conflict-free)
#define MAXIT 200
#define EPS_F 0.1f
#define SMALL_F 1e-20f
#define CONV_TOL 1e-6f

typedef unsigned long long u64;

__device__ unsigned g_maxEnc;
__device__ unsigned g_minEnc;
__device__ int      g_anyMask;
__device__ float    g_alpha;
__device__ float    g_filled;
__device__ float    g_normPart[BSZ];

__device__ __forceinline__ float neg_inf_f(){ return __int_as_float(0xff800000); }

__device__ __forceinline__ u64 pack2(float lo, float hi){
  u64 r; asm("mov.b64 %0, {%1,%2};" : "=l"(r) : "f"(lo), "f"(hi)); return r;
}
__device__ __forceinline__ void unpack2(u64 v, float& lo, float& hi){
  asm("mov.b64 {%0,%1}, %2;" : "=f"(lo), "=f"(hi) : "l"(v));
}
__device__ __forceinline__ u64 fma2(u64 a, u64 b, u64 c){
  u64 d; asm("fma.rn.f32x2 %0, %1, %2, %3;" : "=l"(d) : "l"(a), "l"(b), "l"(c)); return d;
}
__device__ __forceinline__ u64 mul2(u64 a, u64 b){
  u64 d; asm("mul.rn.f32x2 %0, %1, %2;" : "=l"(d) : "l"(a), "l"(b)); return d;
}
__device__ __forceinline__ u64 add2(u64 a, u64 b){
  u64 d; asm("add.rn.f32x2 %0, %1, %2;" : "=l"(d) : "l"(a), "l"(b)); return d;
}

// order-preserving float->uint encoding (monotone increasing)
__device__ __forceinline__ unsigned encF(float f){
  unsigned u = __float_as_uint(f);
  return (u & 0x80000000u) ? ~u : (u | 0x80000000u);
}
__device__ __forceinline__ float decF(unsigned e){
  unsigned u = (e & 0x80000000u) ? (e & 0x7fffffffu) : ~e;
  return __uint_as_float(u);
}

__global__ void k_init(){
  g_maxEnc = 0u;
  g_minEnc = 0xffffffffu;
  g_anyMask = 0;
}

__global__ void k_reduce(const float* __restrict__ s){
  int i = blockIdx.x * blockDim.x + threadIdx.x;
  int stride = gridDim.x * blockDim.x;
  unsigned mx = 0u, mn = 0xffffffffu;
  unsigned any = 0u;
  float ninf = neg_inf_f();
  for (; i < BSZ*NN; i += stride){
    float x = s[i];
    bool neg = (x == ninf);
    any |= (neg ? 1u : 0u);
    unsigned e = encF(x);
    mx = max(mx, e);
    mn = min(mn, neg ? 0xffffffffu : e);
  }
  mx  = __reduce_max_sync(0xffffffffu, mx);
  mn  = __reduce_min_sync(0xffffffffu, mn);
  any = __reduce_or_sync (0xffffffffu, any);
  if ((threadIdx.x & 31) == 0){
    atomicMax(&g_maxEnc, mx);
    atomicMin(&g_minEnc, mn);
    if (any) atomicOr(&g_anyMask, 1);
  }
}

__global__ void k_params(){
  float maxS = decF(g_maxEnc);
  float minS = decF(g_minEnc);
  float filled = minS - (maxS - minS);
  float minF = g_anyMask ? fminf(filled, minS) : minS;
  float maxF = fmaxf(maxS, minF);
  float c1 = minF*minF, c2 = maxF*maxF;
  float c3 = (minF-64.f)*(minF-64.f), c4 = (maxF-64.f)*(maxF-64.f);
  float cmax = fmaxf(fmaxf(c1,c2), fmaxf(c3,c4));
  g_alpha  = 1.f/(EPS_F*cmax);
  g_filled = filled;
}

__global__ void __launch_bounds__(NT, 2) k_main(
    const float* __restrict__ scores,
    const float* __restrict__ W,
    float* __restrict__ out)
{
  __shared__ float sh_s[NN];
  __shared__ float sh_red[KP1*RSTR];   // loop: 65 rows x 64 partials (stride 65); reused as sort buffer
  __shared__ float sh_coef[KP1];       // coef[a] = cE[a]*v[64-a]
  __shared__ float sh_tk[KK];
  __shared__ float sh_invZn[KK];
  __shared__ float sh_wred[NWARP];
  __shared__ float sh_scalar[1];
  __shared__ int   sh_conv[2];

  const int b    = blockIdx.x;
  const int tid  = threadIdx.x;
  const int wid  = tid >> 5;
  const int lane = tid & 31;
  const float alpha  = g_alpha;
  const float filled = g_filled;
  const float MU = 1.f/(float)NN;
  const float ninf = neg_inf_f();

  const float* sc = scores + (size_t)b*NN;

  #pragma unroll
  for (int j=0;j<RPT;j++){
    int n = tid + j*NT;
    float x = sc[n];
    if (x == ninf) x = filled;
    sh_s[n] = x;
  }
  if (tid < KP1){
    float a  = (float)tid;
    sh_coef[tid] = __expf(-alpha*a*a) * (1.f/(float)KP1);  // cE[a] * v0, v0 = 1/65
  }
  if (tid == 0){ sh_conv[0] = 0; sh_conv[1] = 0; }
  __syncthreads();

  // w_n = exp(2*alpha*s_n), packed in pairs
  u64 w2[RPT/2];
  #pragma unroll
  for (int q=0;q<RPT/2;q++){
    float wa = __expf(2.f*alpha*sh_s[tid + (2*q  )*NT]);
    float wb = __expf(2.f*alpha*sh_s[tid + (2*q+1)*NT]);
    w2[q] = pack2(wa, wb);
  }

  float oldc = (tid < KP1) ? sh_coef[tid] : 0.f;
  u64 y2[RPT/2];

  // ================= Sinkhorn iterations (early-exit at fp32 fixed point) =============
  #pragma unroll 1
  for (int it=0; it<MAXIT; ++it){
    // ---- u-update: acc = sum_a coef[a]*w^a (Horner, packed), y = MU/acc ----
    {
      float c64 = sh_coef[KK];
      u64 acc2[RPT/2];
      #pragma unroll
      for (int q=0;q<RPT/2;q++) acc2[q] = pack2(c64, c64);
      #pragma unroll
      for (int a=KK-1;a>=0;--a){
        float f = sh_coef[a];
        u64 f2 = pack2(f, f);
        #pragma unroll
        for (int q=0;q<RPT/2;q++) acc2[q] = fma2(acc2[q], w2[q], f2);
      }
      #pragma unroll
      for (int q=0;q<RPT/2;q++){
        float lo, hi; unpack2(acc2[q], lo, hi);
        y2[q] = pack2(__fdividef(MU, lo), __fdividef(MU, hi));
      }
    }

    // ---- v-update power sums m_a = sum_n y_n w_n^a ----
    {
      u64 t2[RPT/2];
      #pragma unroll
      for (int q=0;q<RPT/2;q++) t2[q] = y2[q];
      #pragma unroll
      for (int a=0;a<KP1;a++){
        u64 p = add2(add2(t2[0], t2[1]), add2(t2[2], t2[3]));
        float lo, hi; unpack2(p, lo, hi);
        float mv = lo + hi;
        mv += __shfl_xor_sync(0xffffffffu, mv, 16);
        mv += __shfl_xor_sync(0xffffffffu, mv, 8);
        if (lane < 8) sh_red[a*RSTR + wid*8 + lane] = mv;
        if (a < KK){
          #pragma unroll
          for (int q=0;q<RPT/2;q++) t2[q] = mul2(t2[q], w2[q]);
        }
      }
    }
    __syncthreads();

    if (tid < KP1){
      float mm = 0.f;
      const float* row = &sh_red[tid*RSTR];
      #pragma unroll
      for (int p=0;p<NWARP*8;p++) mm += row[p];
      float nuv = (tid==0) ? ((float)(NN-KK)/(float)NN) : MU;
      float newc = __fdividef(nuv, mm);          // cE cancels algebraically
      sh_coef[tid] = newc;
      if (fabsf(newc - oldc) > CONV_TOL*fabsf(oldc)) sh_conv[it&1] = 1;
      oldc = newc;
      if (tid == 0) sh_conv[(it+1)&1] = 0;
    }
    __syncthreads();
    if (sh_conv[it&1] == 0) break;               // all coefs at fixed point
  }

  // ================= sort s (bitonic, ascending) in sh_red =================
  float* sh_sort = sh_red;
  #pragma unroll
  for (int j=0;j<RPT;j++) sh_sort[tid+j*NT] = sh_s[tid+j*NT];
  __syncthreads();
  for (int kk2=2; kk2<=NN; kk2<<=1){
    for (int jj=kk2>>1; jj>0; jj>>=1){
      #pragma unroll
      for (int j=0;j<RPT;j++){
        int i = tid + j*NT;
        int ixj = i ^ jj;
        if (ixj > i){
          float va = sh_sort[i], vb = sh_sort[ixj];
          bool asc = ((i & kk2) == 0);
          if ((va > vb) == asc){ sh_sort[i]=vb; sh_sort[ixj]=va; }
        }
      }
      __syncthreads();
    }
  }

  // ================= tau and top-k =================
  {
    float part = 0.f;
    #pragma unroll
    for (int j=0;j<RPT;j++){ int n=tid+j*NT; part += sh_sort[n]*W[n]; }
    #pragma unroll
    for (int o=16;o>0;o>>=1) part += __shfl_xor_sync(0xffffffffu, part, o);
    if (lane==0) sh_wred[wid] = part;
    __syncthreads();
    if (tid==0){
      float tau=0.f;
      #pragma unroll
      for (int q=0;q<NWARP;q++) tau += sh_wred[q];
      sh_scalar[0] = 1.f/tau;
    }
    if (tid < KK) sh_tk[tid] = sh_sort[NN-1-tid];   // descending top-K
    __syncthreads();
  }
  const float invTau = sh_scalar[0];

  // ================= Gamma0 column sums Z_k (chunked to keep regs low) ============
  #pragma unroll 1
  for (int c=0;c<KK/16;c++){
    float z[16];
    #pragma unroll
    for (int q=0;q<16;q++) z[q]=0.f;
    #pragma unroll
    for (int j=0;j<RPT;j++){
      float sv = sh_s[tid+j*NT];
      #pragma unroll
      for (int q=0;q<16;q++){
        float d = fabsf(sh_tk[c*16+q]-sv);
        float e = __expf(d*invTau);               // sigmoid(-d/tau) = 1/(1+e)
        z[q] += __fdividef(1.f, 1.f+e) + SMALL_F;
      }
    }
    #pragma unroll
    for (int q=0;q<16;q++){
      float mv = z[q];
      #pragma unroll
      for (int o=16;o>0;o>>=1) mv += __shfl_xor_sync(0xffffffffu, mv, o);
      if (lane==0) sh_wred[wid] = mv;   // reuse: one anchor at a time per pass would serialize; store per (q,wid)
      // instead: store to sh_red region (free after sort usage this pass? sh_sort no longer needed)
      if (lane==0) sh_red[q*NWARP + wid] = mv;
    }
    __syncthreads();
    if (tid < 16){
      float Z=0.f;
      #pragma unroll
      for (int q=0;q<NWARP;q++) Z += sh_red[tid*NWARP+q];
      sh_invZn[c*16+tid] = __fdividef(1.f, Z*(float)NN);
    }
    __syncthreads();
  }

  // ================= final: Gamma, A, ||Gamma - Gamma0|| =================
  float nrm = 0.f;
  #pragma unroll 1
  for (int j=0;j<RPT;j++){
    int n = tid + j*NT;
    float sv = sh_s[n];
    float yj, wj;
    { float lo,hi;
      unpack2(y2[j>>1], lo, hi); yj = (j&1)?hi:lo;
      unpack2(w2[j>>1], lo, hi); wj = (j&1)?hi:lo; }
    float* orow = out + ((size_t)b*NN + n)*KK;
    float gam64 = yj * sh_coef[0];               // k=64 column (a=0), norm only
    float t  = wj;                               // w^a, a starting at 1
    float rs = 0.f;
    #pragma unroll 1
    for (int g=0;g<16;g++){                      // anchors a = 4g+1 .. 4g+4 -> k = 63-4g .. 60-4g
      float gv[4];
      #pragma unroll
      for (int m=0;m<4;m++){
        int a = 4*g + 1 + m;
        int k = KK - a;
        float gam = yj*t*sh_coef[a];
        gv[m] = gam;
        float d  = fabsf(sh_tk[k]-sv);
        float e  = __expf(d*invTau);
        float g0 = (__fdividef(1.f,1.f+e)+SMALL_F)*sh_invZn[k];
        rs += g0;
        float df = gam - g0;
        nrm = fmaf(df,df,nrm);
        t *= wj;
      }
      float4 o4 = make_float4(gv[3]*(float)NN, gv[2]*(float)NN,
                              gv[1]*(float)NN, gv[0]*(float)NN);
      *reinterpret_cast<float4*>(orow + (60 - 4*g)) = o4;   // k0 = 60-4g
    }
    float last = 1.f/(float)NN - rs;
    last = fminf(fmaxf(last, SMALL_F), 1.f-SMALL_F);
    float dl = gam64 - last;
    nrm = fmaf(dl,dl,nrm);
  }
  #pragma unroll
  for (int o=16;o>0;o>>=1) nrm += __shfl_xor_sync(0xffffffffu, nrm, o);
  if (lane==0) sh_wred[wid] = nrm;
  __syncthreads();
  if (tid==0){
    float s=0.f;
    #pragma unroll
    for (int q=0;q<NWARP;q++) s += sh_wred[q];
    g_normPart[b] = s;
  }
}

__global__ void k_norm(float* __restrict__ out){
  float s = 0.f;
  for (int b=0;b<BSZ;b++) s += g_normPart[b];   // fixed order -> deterministic
  out[(size_t)BSZ*NN*KK] = sqrtf(s);
}

extern "C" void kernel_launch(void* const* d_in, const int* in_sizes, int n_in,
                              void* d_out, int out_size)
{
  const float* scores = (const float*)d_in[0];
  const float* W      = (const float*)d_in[1];
  if (n_in >= 2 && in_sizes[0] == NN && in_sizes[1] == BSZ*NN){
    const float* tmp = scores; scores = W; W = tmp;   // defensive input-order swap
  }
  float* out = (float*)d_out;
  (void)out_size;

  k_init  <<<1, 1>>>();
  k_reduce<<<256, 256>>>(scores);
  k_params<<<1, 1>>>();
  k_main  <<<BSZ, NT>>>(scores, W, out);
  k_norm  <<<1, 1>>>(out);
}

// round 4
// speedup vs baseline: 1.1629x; 1.1629x over previous
#include <cuda_runtime.h>
#include <cstddef>

#define BSZ   256
#define NN    2048
#define KK    64
#define KP1   65
#define NT    256
#define RPT   8
#define NWARP 8
#define RSTR  65
#define MAXIT 200
#define EPS_F 0.1f
#define SMALL_F 1e-20f
#define CONV_TOL 2e-6f
#define PREB  64
#define MU_F  (1.f/2048.f)

typedef unsigned long long u64;

__device__ unsigned g_bMax[PREB];
__device__ unsigned g_bMin[PREB];
__device__ unsigned g_bAny[PREB];
__device__ int      g_ticket = 0;
__device__ float    g_alpha;
__device__ float    g_filled;
__device__ float    g_normPart[BSZ];

__device__ __forceinline__ u64 pack2(float lo, float hi){
  u64 r; asm("mov.b64 %0, {%1,%2};" : "=l"(r) : "f"(lo), "f"(hi)); return r;
}
__device__ __forceinline__ void unpack2(u64 v, float& lo, float& hi){
  asm("mov.b64 {%0,%1}, %2;" : "=f"(lo), "=f"(hi) : "l"(v));
}
__device__ __forceinline__ u64 fma2(u64 a, u64 b, u64 c){
  u64 d; asm("fma.rn.f32x2 %0, %1, %2, %3;" : "=l"(d) : "l"(a), "l"(b), "l"(c)); return d;
}
__device__ __forceinline__ u64 mul2(u64 a, u64 b){
  u64 d; asm("mul.rn.f32x2 %0, %1, %2;" : "=l"(d) : "l"(a), "l"(b)); return d;
}
__device__ __forceinline__ u64 add2(u64 a, u64 b){
  u64 d; asm("add.rn.f32x2 %0, %1, %2;" : "=l"(d) : "l"(a), "l"(b)); return d;
}
__device__ __forceinline__ float tanhA(float x){
  float r; asm("tanh.approx.f32 %0, %1;" : "=f"(r) : "f"(x)); return r;
}
__device__ __forceinline__ unsigned encF(float f){
  unsigned u = __float_as_uint(f);
  return (u & 0x80000000u) ? ~u : (u | 0x80000000u);
}
__device__ __forceinline__ float decF(unsigned e){
  unsigned u = (e & 0x80000000u) ? (e & 0x7fffffffu) : ~e;
  return __uint_as_float(u);
}

__global__ void k_pre(const float* __restrict__ s){
  __shared__ unsigned sMax[8], sMin[8], sAny[8];
  int tid = threadIdx.x;
  unsigned mx=0u, mn=0xffffffffu, any=0u;
  const float ninf = __int_as_float(0xff800000);
  for (int i = blockIdx.x*256 + tid; i < BSZ*NN; i += PREB*256){
    float x = s[i];
    bool neg = (x==ninf);
    any |= (neg?1u:0u);
    unsigned e = encF(x);
    mx = max(mx,e);
    mn = min(mn, neg?0xffffffffu:e);
  }
  mx=__reduce_max_sync(0xffffffffu,mx);
  mn=__reduce_min_sync(0xffffffffu,mn);
  any=__reduce_or_sync(0xffffffffu,any);
  if ((tid&31)==0){ sMax[tid>>5]=mx; sMin[tid>>5]=mn; sAny[tid>>5]=any; }
  __syncthreads();
  if (tid==0){
    #pragma unroll
    for (int q=1;q<8;q++){ mx=max(mx,sMax[q]); mn=min(mn,sMin[q]); any|=sAny[q]; }
    g_bMax[blockIdx.x]=mx; g_bMin[blockIdx.x]=mn; g_bAny[blockIdx.x]=any;
    __threadfence();
    if (atomicAdd(&g_ticket,1) == PREB-1){
      __threadfence();
      unsigned MX=0u, MN=0xffffffffu, AN=0u;
      for (int q=0;q<PREB;q++){ MX=max(MX,g_bMax[q]); MN=min(MN,g_bMin[q]); AN|=g_bAny[q]; }
      float maxS=decF(MX), minS=decF(MN);
      float filled = minS-(maxS-minS);
      float minF = AN ? fminf(filled,minS) : minS;
      float maxF = fmaxf(maxS,minF);
      float c1=minF*minF, c2=maxF*maxF;
      float c3=(minF-64.f)*(minF-64.f), c4=(maxF-64.f)*(maxF-64.f);
      float cmax=fmaxf(fmaxf(c1,c2),fmaxf(c3,c4));
      g_alpha  = 1.f/(EPS_F*cmax);
      g_filled = filled;
      g_ticket = 0;
    }
  }
}

__global__ void __launch_bounds__(NT, 2) k_main(
    const float* __restrict__ scores,
    const float* __restrict__ W,
    float* __restrict__ out)
{
  __shared__ __align__(16) float sh_s[NN];
  __shared__ __align__(16) float sh_red[RSTR*KP1];
  __shared__ __align__(16) float sh_coef[KP1+3];
  __shared__ float sh_tk[KK];
  __shared__ float sh_invZn[KK];
  __shared__ float sh_wred[NWARP];
  __shared__ float sh_scalar[1];
  __shared__ int   sh_conv[2];

  const int tid  = threadIdx.x;
  const int wid  = tid >> 5;
  const int lane = tid & 31;
  const int b    = blockIdx.x;
  const float alpha  = g_alpha;
  const float filled = g_filled;
  const float ninf = __int_as_float(0xff800000);
  const float* sc = scores + (size_t)b*NN;

  #pragma unroll
  for (int j=0;j<RPT;j++){
    int n = tid + j*NT;
    float x = sc[n];
    if (x == ninf) x = filled;
    sh_s[n] = x;
  }
  if (tid < KP1){
    float a = (float)tid;
    sh_coef[tid] = __expf(-alpha*a*a) * (1.f/(float)KP1);
  }
  if (tid == 0){ sh_conv[0]=0; sh_conv[1]=0; }
  __syncthreads();

  u64 w2[4];
  #pragma unroll
  for (int q=0;q<4;q++){
    float wa = __expf(2.f*alpha*sh_s[tid + (2*q  )*NT]);
    float wb = __expf(2.f*alpha*sh_s[tid + (2*q+1)*NT]);
    w2[q] = pack2(wa, wb);
  }

  float oldc = (tid < KP1) ? sh_coef[tid] : 0.f;
  float h0 = oldc, h1 = oldc;
  u64 y2[4];

  // ============ Sinkhorn loop: Horner u-update + power-sum v-update ============
  #pragma unroll 1
  for (int it=0; it<MAXIT; ++it){
    {
      float c64 = sh_coef[KK];
      u64 a0,a1,a2,a3;
      a0=a1=a2=a3=pack2(c64,c64);
      const float4* cf4 = (const float4*)sh_coef;
      #pragma unroll
      for (int q4=15; q4>=0; --q4){
        float4 cc = cf4[q4];
        u64 f;
        f=pack2(cc.w,cc.w); a0=fma2(a0,w2[0],f); a1=fma2(a1,w2[1],f); a2=fma2(a2,w2[2],f); a3=fma2(a3,w2[3],f);
        f=pack2(cc.z,cc.z); a0=fma2(a0,w2[0],f); a1=fma2(a1,w2[1],f); a2=fma2(a2,w2[2],f); a3=fma2(a3,w2[3],f);
        f=pack2(cc.y,cc.y); a0=fma2(a0,w2[0],f); a1=fma2(a1,w2[1],f); a2=fma2(a2,w2[2],f); a3=fma2(a3,w2[3],f);
        f=pack2(cc.x,cc.x); a0=fma2(a0,w2[0],f); a1=fma2(a1,w2[1],f); a2=fma2(a2,w2[2],f); a3=fma2(a3,w2[3],f);
      }
      float lo,hi;
      unpack2(a0,lo,hi); y2[0]=pack2(__fdividef(MU_F,lo), __fdividef(MU_F,hi));
      unpack2(a1,lo,hi); y2[1]=pack2(__fdividef(MU_F,lo), __fdividef(MU_F,hi));
      unpack2(a2,lo,hi); y2[2]=pack2(__fdividef(MU_F,lo), __fdividef(MU_F,hi));
      unpack2(a3,lo,hi); y2[3]=pack2(__fdividef(MU_F,lo), __fdividef(MU_F,hi));
    }
    {
      u64 t0=y2[0], t1=y2[1], t2=y2[2], t3=y2[3];
      #pragma unroll
      for (int a=0;a<KP1;a++){
        u64 p = add2(add2(t0,t1), add2(t2,t3));
        float lo,hi; unpack2(p,lo,hi);
        float mv = lo + hi;
        mv += __shfl_xor_sync(0xffffffffu, mv, 16);
        mv += __shfl_xor_sync(0xffffffffu, mv, 8);
        if (lane < 8) sh_red[a*RSTR + wid*8 + lane] = mv;
        if (a < KK){
          t0=mul2(t0,w2[0]); t1=mul2(t1,w2[1]); t2=mul2(t2,w2[2]); t3=mul2(t3,w2[3]);
        }
      }
    }
    __syncthreads();
    if (tid < KP1){
      const float* row = &sh_red[tid*RSTR];
      float s0=0.f,s1=0.f,s2=0.f,s3=0.f;
      #pragma unroll
      for (int p=0;p<64;p+=4){ s0+=row[p]; s1+=row[p+1]; s2+=row[p+2]; s3+=row[p+3]; }
      float mm = (s0+s1)+(s2+s3);
      float nuv = (tid==0) ? ((float)(NN-KK)/(float)NN) : MU_F;
      float newc = __fdividef(nuv, mm);
      if (fabsf(newc - oldc) > CONV_TOL*fabsf(oldc)) sh_conv[it&1] = 1;
      float store = newc;
      if ((it & 3) == 3){                       // Aitken delta-squared (guarded)
        float d1 = h1 - h0, d2 = newc - h1;
        float den = d2 - d1;
        if (fabsf(den) > 1e-30f){
          float ext = newc - (d2*d2)/den;
          if (ext > 0.f && isfinite(ext)) store = ext;
        }
      }
      sh_coef[tid] = store;
      h0 = h1; h1 = store; oldc = store;
      if (tid == 0) sh_conv[(it+1)&1] = 0;
    }
    __syncthreads();
    if (sh_conv[it&1] == 0) break;
  }

  // ============ hybrid bitonic sort: 8 consecutive elems per thread ============
  float sv[8];
  const int base8 = tid*8;
  {
    float4 p0 = *(const float4*)&sh_s[base8];
    float4 p1 = *(const float4*)&sh_s[base8+4];
    sv[0]=p0.x; sv[1]=p0.y; sv[2]=p0.z; sv[3]=p0.w;
    sv[4]=p1.x; sv[5]=p1.y; sv[6]=p1.z; sv[7]=p1.w;
  }
  for (int kk2=2; kk2<=NN; kk2<<=1){
    for (int jj=kk2>>1; jj>=256; jj>>=1){        // cross-warp via SMEM
      *(float4*)&sh_red[base8]   = make_float4(sv[0],sv[1],sv[2],sv[3]);
      *(float4*)&sh_red[base8+4] = make_float4(sv[4],sv[5],sv[6],sv[7]);
      __syncthreads();
      int delta = jj>>3;
      int pc = tid ^ delta;
      bool tmin = (((base8 & kk2)==0) == ((tid & delta)==0));
      float4 q0 = *(const float4*)&sh_red[pc*8];
      float4 q1 = *(const float4*)&sh_red[pc*8+4];
      float o[8] = {q0.x,q0.y,q0.z,q0.w,q1.x,q1.y,q1.z,q1.w};
      #pragma unroll
      for (int m=0;m<8;m++) sv[m] = tmin ? fminf(sv[m],o[m]) : fmaxf(sv[m],o[m]);
      __syncthreads();
    }
    {
      int jj0 = (kk2>>1) > 128 ? 128 : (kk2>>1);  // in-warp via shfl
      for (int jj=jj0; jj>=8; jj>>=1){
        int delta = jj>>3;
        bool tmin = (((base8 & kk2)==0) == ((tid & delta)==0));
        #pragma unroll
        for (int m=0;m<8;m++){
          float o = __shfl_xor_sync(0xffffffffu, sv[m], delta);
          sv[m] = tmin ? fminf(sv[m],o) : fmaxf(sv[m],o);
        }
      }
    }
    {
      int jj0 = (kk2>>1) > 4 ? 4 : (kk2>>1);      // in-register
      for (int jj=jj0; jj>=1; jj>>=1){
        #pragma unroll
        for (int m=0;m<8;m++){
          if ((m & jj)==0){
            int m2 = m | jj;
            bool asc = (((base8+m) & kk2)==0);
            float a=sv[m], bb=sv[m2];
            if ((a>bb)==asc){ sv[m]=bb; sv[m2]=a; }
          }
        }
      }
    }
  }

  // ============ tau + top-K ============
  {
    float4 w0 = *(const float4*)&W[base8];
    float4 w1 = *(const float4*)&W[base8+4];
    float part = sv[0]*w0.x + sv[1]*w0.y + sv[2]*w0.z + sv[3]*w0.w
               + sv[4]*w1.x + sv[5]*w1.y + sv[6]*w1.z + sv[7]*w1.w;
    #pragma unroll
    for (int o=16;o>0;o>>=1) part += __shfl_xor_sync(0xffffffffu, part, o);
    if (lane==0) sh_wred[wid] = part;
    if (tid >= NT-8){                             // top-64 live in last 8 threads
      #pragma unroll
      for (int m=0;m<8;m++) sh_tk[NN-1-base8-m] = sv[m];
    }
    __syncthreads();
    if (tid==0){
      float tau=0.f;
      #pragma unroll
      for (int q=0;q<NWARP;q++) tau += sh_wred[q];
      sh_scalar[0] = 0.5f/tau;
    }
    __syncthreads();
  }
  const float hTau = sh_scalar[0];                // 0.5/tau (sign preserved)

  // ============ Gamma0 column sums Z_k (tanh sigmoid) ============
  #pragma unroll 1
  for (int c=0;c<4;c++){
    float z[16];
    #pragma unroll
    for (int q=0;q<16;q++) z[q]=0.f;
    #pragma unroll
    for (int j=0;j<RPT;j++){
      float s = sh_s[tid+j*NT];
      #pragma unroll
      for (int q=0;q<16;q++){
        float d = fabsf(sh_tk[c*16+q]-s);
        float sg = fmaf(-0.5f, tanhA(d*hTau), 0.5f);  // sigmoid(-d/tau)
        z[q] += sg + SMALL_F;
      }
    }
    #pragma unroll
    for (int q=0;q<16;q++){
      float mv = z[q];
      #pragma unroll
      for (int o=16;o>0;o>>=1) mv += __shfl_xor_sync(0xffffffffu, mv, o);
      if (lane==0) sh_red[q*NWARP + wid] = mv;
    }
    __syncthreads();
    if (tid < 16){
      float Z=0.f;
      #pragma unroll
      for (int q=0;q<NWARP;q++) Z += sh_red[tid*NWARP+q];
      sh_invZn[c*16+tid] = __fdividef(1.f, Z*(float)NN);
    }
    __syncthreads();
  }

  // ============ final: Gamma, A, ||Gamma-Gamma0||^2 ============
  float nrm = 0.f;
  #pragma unroll 1
  for (int j=0;j<RPT;j++){
    int n = tid + j*NT;
    float s = sh_s[n];
    float yj, wj;
    { float lo,hi;
      unpack2(y2[j>>1], lo, hi); yj = (j&1)?hi:lo;
      unpack2(w2[j>>1], lo, hi); wj = (j&1)?hi:lo; }
    float* orow = out + ((size_t)b*NN + n)*KK;
    float gam64 = yj * sh_coef[0];
    float t  = wj;
    float rs = 0.f;
    #pragma unroll 1
    for (int g=0;g<16;g++){
      float gv[4];
      #pragma unroll
      for (int m=0;m<4;m++){
        int a = 4*g + 1 + m;
        int k = KK - a;
        float gam = yj*t*sh_coef[a];
        gv[m] = gam;
        float d  = fabsf(sh_tk[k]-s);
        float sg = fmaf(-0.5f, tanhA(d*hTau), 0.5f);
        float g0 = (sg + SMALL_F)*sh_invZn[k];
        rs += g0;
        float df = gam - g0;
        nrm = fmaf(df,df,nrm);
        t *= wj;
      }
      *(float4*)(orow + (60 - 4*g)) =
        make_float4(gv[3]*(float)NN, gv[2]*(float)NN, gv[1]*(float)NN, gv[0]*(float)NN);
    }
    float last = MU_F - rs;
    last = fminf(fmaxf(last, SMALL_F), 1.f-SMALL_F);
    float dl = gam64 - last;
    nrm = fmaf(dl,dl,nrm);
  }
  #pragma unroll
  for (int o=16;o>0;o>>=1) nrm += __shfl_xor_sync(0xffffffffu, nrm, o);
  if (lane==0) sh_wred[wid] = nrm;
  __syncthreads();
  if (tid==0){
    float sA=0.f;
    #pragma unroll
    for (int q=0;q<NWARP;q++) sA += sh_wred[q];
    g_normPart[b] = sA;
  }
}

__global__ void k_norm(float* __restrict__ out){
  float s = 0.f;
  for (int b=0;b<BSZ;b++) s += g_normPart[b];
  out[(size_t)BSZ*NN*KK] = sqrtf(s);
}

extern "C" void kernel_launch(void* const* d_in, const int* in_sizes, int n_in,
                              void* d_out, int out_size)
{
  const float* scores = (const float*)d_in[0];
  const float* W      = (const float*)d_in[1];
  if (n_in >= 2 && in_sizes[0] == NN && in_sizes[1] == BSZ*NN){
    const float* tmp = scores; scores = W; W = tmp;
  }
  float* out = (float*)d_out;
  (void)out_size;

  k_pre <<<PREB, 256>>>(scores);
  k_main<<<BSZ, NT>>>(scores, W, out);
  k_norm<<<1, 1>>>(out);
}

// round 5
// speedup vs baseline: 1.2562x; 1.0802x over previous
#include <cuda_runtime.h>
#include <cstddef>

#define BSZ   256
#define NN    2048
#define KK    64
#define KP1   65
#define NT    256
#define RPT   8
#define NWARP 8
#define RSTR  129
#define MAXIT 200
#define EPS_F 0.1f
#define CONV_TOL 1e-5f
#define MU_F  (1.f/2048.f)

typedef unsigned long long u64;

__device__ unsigned g_maxEnc = 0u;
__device__ unsigned g_minEnc = 0xffffffffu;
__device__ int      g_anyMask = 0;
__device__ int      g_t1 = 0;
__device__ int      g_t2 = 0;
__device__ int      g_phase = 0;
__device__ float    g_alpha;
__device__ float    g_filled;
__device__ float    g_normPart[BSZ];

__device__ __forceinline__ u64 pack2(float lo, float hi){
  u64 r; asm("mov.b64 %0, {%1,%2};" : "=l"(r) : "f"(lo), "f"(hi)); return r;
}
__device__ __forceinline__ void unpack2(u64 v, float& lo, float& hi){
  asm("mov.b64 {%0,%1}, %2;" : "=f"(lo), "=f"(hi) : "l"(v));
}
__device__ __forceinline__ u64 fma2(u64 a, u64 b, u64 c){
  u64 d; asm("fma.rn.f32x2 %0, %1, %2, %3;" : "=l"(d) : "l"(a), "l"(b), "l"(c)); return d;
}
__device__ __forceinline__ u64 mul2(u64 a, u64 b){
  u64 d; asm("mul.rn.f32x2 %0, %1, %2;" : "=l"(d) : "l"(a), "l"(b)); return d;
}
__device__ __forceinline__ u64 add2(u64 a, u64 b){
  u64 d; asm("add.rn.f32x2 %0, %1, %2;" : "=l"(d) : "l"(a), "l"(b)); return d;
}
__device__ __forceinline__ float tanhA(float x){
  float r; asm("tanh.approx.f32 %0, %1;" : "=f"(r) : "f"(x)); return r;
}
__device__ __forceinline__ unsigned encF(float f){
  unsigned u = __float_as_uint(f);
  return (u & 0x80000000u) ? ~u : (u | 0x80000000u);
}
__device__ __forceinline__ float decF(unsigned e){
  unsigned u = (e & 0x80000000u) ? (e & 0x7fffffffu) : ~e;
  return __uint_as_float(u);
}

__global__ void __launch_bounds__(NT, 2) k_all(
    const float* __restrict__ scores,
    const float* __restrict__ W,
    float* __restrict__ out)
{
  __shared__ __align__(16) float sh_s[NN];
  __shared__ __align__(16) float sh_red[KP1*RSTR];
  __shared__ __align__(16) float sh_coef[KP1+3];
  __shared__ u64   sh_cp[KK/2];
  __shared__ u64   sh_izp[KK/2];
  __shared__ float sh_tk[KK];
  __shared__ float sh_invZn[KK];
  __shared__ float sh_wred[NWARP];
  __shared__ float sh_par[2];
  __shared__ float sh_scalar[1];
  __shared__ unsigned sMx[NWARP], sMn[NWARP], sAn[NWARP];
  __shared__ int   sh_conv[2];
  __shared__ int   sh_last;

  const int tid  = threadIdx.x;
  const int wid  = tid >> 5;
  const int lane = tid & 31;
  const int b    = blockIdx.x;
  const float ninf = __int_as_float(0xff800000);
  const float* sc = scores + (size_t)b*NN;

  // ===== phase A: load + local min/max/any + global params via ticket/spin =====
  unsigned mx=0u, mn=0xffffffffu, any=0u;
  #pragma unroll
  for (int j=0;j<RPT;j++){
    int n = tid + j*NT;
    float x = sc[n];
    sh_s[n] = x;
    bool neg = (x==ninf);
    any |= (neg?1u:0u);
    unsigned e = encF(x);
    mx = max(mx,e);
    mn = min(mn, neg?0xffffffffu:e);
  }
  mx=__reduce_max_sync(0xffffffffu,mx);
  mn=__reduce_min_sync(0xffffffffu,mn);
  any=__reduce_or_sync(0xffffffffu,any);
  if (lane==0){ sMx[wid]=mx; sMn[wid]=mn; sAn[wid]=any; }
  __syncthreads();
  if (tid==0){
    #pragma unroll
    for (int q=1;q<NWARP;q++){ mx=max(mx,sMx[q]); mn=min(mn,sMn[q]); any|=sAn[q]; }
    atomicMax(&g_maxEnc,mx); atomicMin(&g_minEnc,mn);
    if (any) atomicOr(&g_anyMask,1);
    __threadfence();
    if (atomicAdd(&g_t1,1) == BSZ-1){
      unsigned MX=*(volatile unsigned*)&g_maxEnc;
      unsigned MN=*(volatile unsigned*)&g_minEnc;
      int AN=*(volatile int*)&g_anyMask;
      float maxS=decF(MX), minS=decF(MN);
      float filled = minS-(maxS-minS);
      float minF = AN ? fminf(filled,minS) : minS;
      float maxF = fmaxf(maxS,minF);
      float c1=minF*minF, c2=maxF*maxF;
      float c3=(minF-64.f)*(minF-64.f), c4=(maxF-64.f)*(maxF-64.f);
      float cmax=fmaxf(fmaxf(c1,c2),fmaxf(c3,c4));
      *(volatile float*)&g_alpha  = 1.f/(EPS_F*cmax);
      *(volatile float*)&g_filled = filled;
      __threadfence();
      *(volatile int*)&g_phase = 1;
    }
    while (*(volatile int*)&g_phase == 0) __nanosleep(64);
    __threadfence();
    sh_par[0]=*(volatile float*)&g_alpha;
    sh_par[1]=*(volatile float*)&g_filled;
  }
  __syncthreads();
  const float alpha  = sh_par[0];
  const float filled = sh_par[1];

  #pragma unroll
  for (int j=0;j<RPT;j++){
    int n = tid + j*NT;
    float x = sh_s[n];
    if (x == ninf) sh_s[n] = filled;
  }
  if (tid < KP1){
    float a = (float)tid;
    sh_coef[tid] = __expf(-alpha*a*a) * (1.f/(float)KP1);
  }
  if (tid == 0){ sh_conv[0]=0; sh_conv[1]=0; }
  __syncthreads();

  u64 w2[4];
  #pragma unroll
  for (int q=0;q<4;q++){
    float wa = __expf(2.f*alpha*sh_s[tid + (2*q  )*NT]);
    float wb = __expf(2.f*alpha*sh_s[tid + (2*q+1)*NT]);
    w2[q] = pack2(wa, wb);
  }

  float oldc = (tid < KP1) ? sh_coef[tid] : 0.f;
  float h0 = oldc, h1 = oldc;
  u64 y2[4];

  // ===== Sinkhorn loop: Horner u-update + power-sum v-update =====
  #pragma unroll 1
  for (int it=0; it<MAXIT; ++it){
    {
      float c64 = sh_coef[KK];
      u64 a0,a1,a2,a3;
      a0=a1=a2=a3=pack2(c64,c64);
      const float4* cf4 = (const float4*)sh_coef;
      #pragma unroll
      for (int q4=15; q4>=0; --q4){
        float4 cc = cf4[q4];
        u64 f;
        f=pack2(cc.w,cc.w); a0=fma2(a0,w2[0],f); a1=fma2(a1,w2[1],f); a2=fma2(a2,w2[2],f); a3=fma2(a3,w2[3],f);
        f=pack2(cc.z,cc.z); a0=fma2(a0,w2[0],f); a1=fma2(a1,w2[1],f); a2=fma2(a2,w2[2],f); a3=fma2(a3,w2[3],f);
        f=pack2(cc.y,cc.y); a0=fma2(a0,w2[0],f); a1=fma2(a1,w2[1],f); a2=fma2(a2,w2[2],f); a3=fma2(a3,w2[3],f);
        f=pack2(cc.x,cc.x); a0=fma2(a0,w2[0],f); a1=fma2(a1,w2[1],f); a2=fma2(a2,w2[2],f); a3=fma2(a3,w2[3],f);
      }
      float lo,hi;
      unpack2(a0,lo,hi); y2[0]=pack2(__fdividef(MU_F,lo), __fdividef(MU_F,hi));
      unpack2(a1,lo,hi); y2[1]=pack2(__fdividef(MU_F,lo), __fdividef(MU_F,hi));
      unpack2(a2,lo,hi); y2[2]=pack2(__fdividef(MU_F,lo), __fdividef(MU_F,hi));
      unpack2(a3,lo,hi); y2[3]=pack2(__fdividef(MU_F,lo), __fdividef(MU_F,hi));
    }
    {
      u64 t0=y2[0], t1=y2[1], t2=y2[2], t3=y2[3];
      #pragma unroll
      for (int a=0;a<KP1;a++){
        u64 p = add2(add2(t0,t1), add2(t2,t3));
        float lo,hi; unpack2(p,lo,hi);
        float mv = lo + hi;
        mv += __shfl_xor_sync(0xffffffffu, mv, 16);
        if (lane < 16) sh_red[a*RSTR + wid*16 + lane] = mv;
        if (a < KK){
          t0=mul2(t0,w2[0]); t1=mul2(t1,w2[1]); t2=mul2(t2,w2[2]); t3=mul2(t3,w2[3]);
        }
      }
    }
    __syncthreads();
    if (tid < KP1){
      const float* row = &sh_red[tid*RSTR];
      float s0=0.f,s1=0.f,s2=0.f,s3=0.f;
      #pragma unroll
      for (int p=0;p<128;p+=4){ s0+=row[p]; s1+=row[p+1]; s2+=row[p+2]; s3+=row[p+3]; }
      float mm = (s0+s1)+(s2+s3);
      float nuv = (tid==0) ? ((float)(NN-KK)/(float)NN) : MU_F;
      float newc = __fdividef(nuv, mm);
      if (fabsf(newc - oldc) > CONV_TOL*fabsf(oldc)) sh_conv[it&1] = 1;
      float store = newc;
      if ((it & 3) == 3){                        // Aitken delta-squared (guarded)
        float d1 = h1 - h0, d2 = newc - h1;
        float den = d2 - d1;
        if (fabsf(den) > 1e-30f){
          float ext = newc - (d2*d2)/den;
          if (ext > 0.f && isfinite(ext)) store = ext;
        }
      }
      sh_coef[tid] = store;
      h0 = h1; h1 = store; oldc = store;
      if (tid == 0) sh_conv[(it+1)&1] = 0;
    }
    __syncthreads();
    if (sh_conv[it&1] == 0) break;
  }

  // ===== hybrid bitonic sort: 8 consecutive elems per thread =====
  float sv[8];
  const int base8 = tid*8;
  {
    float4 p0 = *(const float4*)&sh_s[base8];
    float4 p1 = *(const float4*)&sh_s[base8+4];
    sv[0]=p0.x; sv[1]=p0.y; sv[2]=p0.z; sv[3]=p0.w;
    sv[4]=p1.x; sv[5]=p1.y; sv[6]=p1.z; sv[7]=p1.w;
  }
  for (int kk2=2; kk2<=NN; kk2<<=1){
    for (int jj=kk2>>1; jj>=256; jj>>=1){
      *(float4*)&sh_red[base8]   = make_float4(sv[0],sv[1],sv[2],sv[3]);
      *(float4*)&sh_red[base8+4] = make_float4(sv[4],sv[5],sv[6],sv[7]);
      __syncthreads();
      int delta = jj>>3;
      int pc = tid ^ delta;
      bool tmin = (((base8 & kk2)==0) == ((tid & delta)==0));
      float4 q0 = *(const float4*)&sh_red[pc*8];
      float4 q1 = *(const float4*)&sh_red[pc*8+4];
      float o[8] = {q0.x,q0.y,q0.z,q0.w,q1.x,q1.y,q1.z,q1.w};
      #pragma unroll
      for (int m=0;m<8;m++) sv[m] = tmin ? fminf(sv[m],o[m]) : fmaxf(sv[m],o[m]);
      __syncthreads();
    }
    {
      int jj0 = (kk2>>1) > 128 ? 128 : (kk2>>1);
      for (int jj=jj0; jj>=8; jj>>=1){
        int delta = jj>>3;
        bool tmin = (((base8 & kk2)==0) == ((tid & delta)==0));
        #pragma unroll
        for (int m=0;m<8;m++){
          float o = __shfl_xor_sync(0xffffffffu, sv[m], delta);
          sv[m] = tmin ? fminf(sv[m],o) : fmaxf(sv[m],o);
        }
      }
    }
    {
      int jj0 = (kk2>>1) > 4 ? 4 : (kk2>>1);
      for (int jj=jj0; jj>=1; jj>>=1){
        #pragma unroll
        for (int m=0;m<8;m++){
          if ((m & jj)==0){
            int m2 = m | jj;
            bool asc = (((base8+m) & kk2)==0);
            float a=sv[m], bb=sv[m2];
            if ((a>bb)==asc){ sv[m]=bb; sv[m2]=a; }
          }
        }
      }
    }
  }

  // ===== tau + top-K =====
  {
    float4 w0 = *(const float4*)&W[base8];
    float4 w1 = *(const float4*)&W[base8+4];
    float part = sv[0]*w0.x + sv[1]*w0.y + sv[2]*w0.z + sv[3]*w0.w
               + sv[4]*w1.x + sv[5]*w1.y + sv[6]*w1.z + sv[7]*w1.w;
    #pragma unroll
    for (int o=16;o>0;o>>=1) part += __shfl_xor_sync(0xffffffffu, part, o);
    if (lane==0) sh_wred[wid] = part;
    if (tid >= NT-8){
      #pragma unroll
      for (int m=0;m<8;m++) sh_tk[NN-1-base8-m] = sv[m];
    }
    __syncthreads();
    if (tid==0){
      float tau=0.f;
      #pragma unroll
      for (int q=0;q<NWARP;q++) tau += sh_wred[q];
      sh_scalar[0] = 0.5f/tau;
    }
    __syncthreads();
  }
  const float hTau = sh_scalar[0];

  // ===== Gamma0 column sums Z_k =====
  #pragma unroll 1
  for (int c=0;c<4;c++){
    float z[16];
    #pragma unroll
    for (int q=0;q<16;q++) z[q]=0.f;
    #pragma unroll
    for (int j=0;j<RPT;j++){
      float s = sh_s[tid+j*NT];
      #pragma unroll
      for (int q=0;q<16;q++){
        float d = fabsf(sh_tk[c*16+q]-s);
        z[q] += fmaf(-0.5f, tanhA(d*hTau), 0.5f);
      }
    }
    #pragma unroll
    for (int q=0;q<16;q++){
      float mv = z[q];
      #pragma unroll
      for (int o=16;o>0;o>>=1) mv += __shfl_xor_sync(0xffffffffu, mv, o);
      if (lane==0) sh_red[q*NWARP + wid] = mv;
    }
    __syncthreads();
    if (tid < 16){
      float Z=0.f;
      #pragma unroll
      for (int q=0;q<NWARP;q++) Z += sh_red[tid*NWARP+q];
      sh_invZn[c*16+tid] = __fdividef(1.f, Z*(float)NN);
    }
    __syncthreads();
  }

  // packed per-pair tables: pair i covers anchors (lo=2i+2 -> k=62-2i, hi=2i+1 -> k=63-2i)
  if (tid < KK/2){
    sh_cp [tid] = pack2(sh_coef[2*tid+2],  sh_coef[2*tid+1]);
    sh_izp[tid] = pack2(sh_invZn[62-2*tid], sh_invZn[63-2*tid]);
  }
  __syncthreads();

  // ===== final: Gamma, A, ||Gamma-Gamma0||^2 (paired f32x2) =====
  const u64 NN2 = pack2(2048.f, 2048.f);
  const u64 MH2 = pack2(-0.5f, -0.5f);
  const u64 PH2 = pack2( 0.5f,  0.5f);
  const u64 M12 = pack2(-1.f, -1.f);
  float nrm = 0.f;
  u64 nrm2 = pack2(0.f, 0.f);
  #pragma unroll 1
  for (int j=0;j<RPT;j++){
    int n = tid + j*NT;
    float s = sh_s[n];
    float yj, wj;
    { float lo,hi;
      unpack2(y2[j>>1], lo, hi); yj = (j&1)?hi:lo;
      unpack2(w2[j>>1], lo, hi); wj = (j&1)?hi:lo; }
    float* orow = out + ((size_t)b*NN + n)*KK;
    float gam64 = yj * sh_coef[0];
    float ww = wj*wj;
    u64 ww2 = pack2(ww, ww);
    float t1v = yj*wj;
    u64 G2 = pack2(t1v*wj, t1v);          // (y*w^2, y*w^1)
    u64 rs2 = pack2(0.f, 0.f);
    #pragma unroll 4
    for (int g=0; g<16; ++g){
      int kb = 60 - 4*g;
      u64 gamP = mul2(G2, sh_cp[2*g]);   G2 = mul2(G2, ww2);
      u64 gamQ = mul2(G2, sh_cp[2*g+1]); G2 = mul2(G2, ww2);
      float thP0 = tanhA(fabsf(sh_tk[kb+2]-s)*hTau);
      float thP1 = tanhA(fabsf(sh_tk[kb+3]-s)*hTau);
      float thQ0 = tanhA(fabsf(sh_tk[kb  ]-s)*hTau);
      float thQ1 = tanhA(fabsf(sh_tk[kb+1]-s)*hTau);
      u64 sgP = fma2(pack2(thP0,thP1), MH2, PH2);
      u64 sgQ = fma2(pack2(thQ0,thQ1), MH2, PH2);
      u64 g0P = mul2(sgP, sh_izp[2*g]);
      u64 g0Q = mul2(sgQ, sh_izp[2*g+1]);
      rs2 = add2(rs2, add2(g0P, g0Q));
      u64 dP = fma2(g0P, M12, gamP);
      u64 dQ = fma2(g0Q, M12, gamQ);
      nrm2 = fma2(dP, dP, nrm2);
      nrm2 = fma2(dQ, dQ, nrm2);
      float ql,qh,pl,ph;
      unpack2(mul2(gamQ, NN2), ql, qh);
      unpack2(mul2(gamP, NN2), pl, ph);
      *(float4*)(orow + kb) = make_float4(ql, qh, pl, ph);
    }
    float rl,rh; unpack2(rs2, rl, rh);
    float last = MU_F - (rl + rh);
    last = fminf(fmaxf(last, 1e-20f), 1.f-1e-20f);
    float dl = gam64 - last;
    nrm = fmaf(dl, dl, nrm);
  }
  { float nl,nh; unpack2(nrm2, nl, nh); nrm += nl + nh; }
  #pragma unroll
  for (int o=16;o>0;o>>=1) nrm += __shfl_xor_sync(0xffffffffu, nrm, o);
  if (lane==0) sh_wred[wid] = nrm;
  __syncthreads();
  if (tid==0){
    float sA=0.f;
    #pragma unroll
    for (int q=0;q<NWARP;q++) sA += sh_wred[q];
    g_normPart[b] = sA;
  }

  // ===== final norm via last-CTA ticket (self-resetting globals) =====
  if (tid==0){
    __threadfence();
    sh_last = (atomicAdd(&g_t2,1) == BSZ-1) ? 1 : 0;
  }
  __syncthreads();
  if (sh_last){
    __threadfence();
    float v = *(volatile float*)&g_normPart[tid];
    #pragma unroll
    for (int o=16;o>0;o>>=1) v += __shfl_xor_sync(0xffffffffu, v, o);
    if (lane==0) sh_wred[wid] = v;
    __syncthreads();
    if (tid==0){
      float sT=0.f;
      #pragma unroll
      for (int q=0;q<NWARP;q++) sT += sh_wred[q];
      out[(size_t)BSZ*NN*KK] = sqrtf(sT);
      g_t1=0; g_t2=0;
      g_maxEnc=0u; g_minEnc=0xffffffffu; g_anyMask=0;
      __threadfence();
      *(volatile int*)&g_phase = 0;
    }
  }
}

extern "C" void kernel_launch(void* const* d_in, const int* in_sizes, int n_in,
                              void* d_out, int out_size)
{
  const float* scores = (const float*)d_in[0];
  const float* W      = (const float*)d_in[1];
  if (n_in >= 2 && in_sizes[0] == NN && in_sizes[1] == BSZ*NN){
    const float* tmp = scores; scores = W; W = tmp;
  }
  float* out = (float*)d_out;
  (void)out_size;

  k_all<<<BSZ, NT>>>(scores, W, out);
}